// round 1
// baseline (speedup 1.0000x reference)
#include <cuda_runtime.h>
#include <cstdint>

#define N_NODES 100000
#define N_EDGES 2048
#define L_TOK 8
#define HID 64
#define D_IN 512      // L_TOK * HID
#define D_GNN 128
#define VOCAB 32000
#define FFN_D 256
#define NROWS (N_EDGES * 2)   // 4096 lm-head rows
#define LBL_OFF 16384          // labels occupy [0, 16384)

// ---------------- device scratch (no allocations allowed) ----------------
__device__ float g_agg[N_NODES * D_GNN];    // 51.2 MB, zero-init; only dst rows ever touched
__device__ float g_edge_h[N_EDGES * D_GNN]; // h[src]+h[dst] per edge
__device__ float g_x[NROWS * HID];          // transformer output
__device__ float g_rowsum[NROWS];           // softmax denominators

// ---------------- K0: zero touched agg rows + row sums ----------------
__global__ void k0_zero(const int* __restrict__ edge_index) {
    int b = blockIdx.x, t = threadIdx.x;
    if (b < N_EDGES) {
        int dst = edge_index[N_EDGES + b];
        g_agg[dst * D_GNN + t] = 0.f;
    } else {
        int i = (b - N_EDGES) * 128 + t;
        if (i < NROWS) g_rowsum[i] = 0.f;
    }
}

// ---------------- K1: msg = (node_emb[src] + edge_emb) @ W_nbr; scatter-add at dst ----------------
__global__ void k1_msg(const int* __restrict__ node_tokens,
                       const int* __restrict__ edge_tokens,
                       const int* __restrict__ edge_index,
                       const float* __restrict__ emb,
                       const float* __restrict__ W_nbr) {
    __shared__ float t_s[16][D_IN];
    __shared__ int s_src[16], s_dst[16];
    int b = blockIdx.x, tid = threadIdx.x;
    int e0 = b * 16;
    if (tid < 16) {
        s_src[tid] = edge_index[e0 + tid];
        s_dst[tid] = edge_index[N_EDGES + e0 + tid];
    }
    __syncthreads();
    for (int el = 0; el < 16; el++) {
        int e = e0 + el;
        int sn = s_src[el];
        for (int idx = tid; idx < D_IN; idx += 128) {
            int l = idx >> 6, h = idx & 63;
            int tn = node_tokens[sn * L_TOK + l];
            int te = edge_tokens[e * L_TOK + l];
            t_s[el][idx] = emb[tn * HID + h] + emb[te * HID + h];
        }
    }
    __syncthreads();
    float acc[16];
#pragma unroll
    for (int el = 0; el < 16; el++) acc[el] = 0.f;
    for (int k = 0; k < D_IN; k++) {
        float w = W_nbr[k * D_GNN + tid];
#pragma unroll
        for (int el = 0; el < 16; el++) acc[el] += t_s[el][k] * w;
    }
#pragma unroll
    for (int el = 0; el < 16; el++)
        atomicAdd(&g_agg[s_dst[el] * D_GNN + tid], acc[el]);
}

// ---------------- K2: h = relu(node_emb @ W_self + agg) at edge endpoints; edge_h = h_src+h_dst ----------------
__global__ void k2_h(const int* __restrict__ node_tokens,
                     const int* __restrict__ edge_index,
                     const float* __restrict__ emb,
                     const float* __restrict__ W_self) {
    __shared__ float ne[16][D_IN];
    __shared__ int s_node[16];
    int b = blockIdx.x, tid = threadIdx.x;
    int e0 = b * 8;
    if (tid < 16) {
        int el = tid & 7;
        s_node[tid] = (tid < 8) ? edge_index[e0 + el] : edge_index[N_EDGES + e0 + el];
    }
    __syncthreads();
    for (int r = 0; r < 16; r++) {
        int n = s_node[r];
        for (int idx = tid; idx < D_IN; idx += 128) {
            int l = idx >> 6, h = idx & 63;
            int tn = node_tokens[n * L_TOK + l];
            ne[r][idx] = emb[tn * HID + h];
        }
    }
    __syncthreads();
    float acc[16];
#pragma unroll
    for (int r = 0; r < 16; r++) acc[r] = 0.f;
    for (int k = 0; k < D_IN; k++) {
        float w = W_self[k * D_GNN + tid];
#pragma unroll
        for (int r = 0; r < 16; r++) acc[r] += ne[r][k] * w;
    }
#pragma unroll
    for (int el = 0; el < 8; el++) {
        float hs = fmaxf(acc[el]     + g_agg[s_node[el]     * D_GNN + tid], 0.f);
        float hd = fmaxf(acc[el + 8] + g_agg[s_node[el + 8] * D_GNN + tid], 0.f);
        g_edge_h[(e0 + el) * D_GNN + tid] = hs + hd;
    }
}

// ---------------- K3: transformer block per edge (S=2, H=64) ----------------
__global__ void k3_xform(const float* __restrict__ Wq, const float* __restrict__ Wk,
                         const float* __restrict__ Wv, const float* __restrict__ Wo,
                         const float* __restrict__ W1, const float* __restrict__ W2) {
    __shared__ float xs[8][2][64];
    __shared__ float qs[8][2][64];
    __shared__ float ks2[8][2][64];
    __shared__ float vs[8][2][64];
    __shared__ float ys[8][2][64];
    __shared__ float hid[8][2][FFN_D];
    __shared__ float att[8][2][2];
    __shared__ float mu[8][2], rs[8][2];
    int b = blockIdx.x, tid = threadIdx.x;
    int e0 = b * 8;
    int s = tid >> 6, c = tid & 63;

#pragma unroll
    for (int el = 0; el < 8; el++)
        xs[el][s][c] = g_edge_h[(e0 + el) * D_GNN + s * 64 + c];
    __syncthreads();

    // q,k,v
    {
        float aq[8], ak[8], av[8];
#pragma unroll
        for (int el = 0; el < 8; el++) { aq[el] = 0.f; ak[el] = 0.f; av[el] = 0.f; }
        for (int k = 0; k < 64; k++) {
            float wq = Wq[k * 64 + c], wk = Wk[k * 64 + c], wv = Wv[k * 64 + c];
#pragma unroll
            for (int el = 0; el < 8; el++) {
                float xv = xs[el][s][k];
                aq[el] += xv * wq; ak[el] += xv * wk; av[el] += xv * wv;
            }
        }
#pragma unroll
        for (int el = 0; el < 8; el++) {
            qs[el][s][c] = aq[el]; ks2[el][s][c] = ak[el]; vs[el][s][c] = av[el];
        }
    }
    __syncthreads();

    // scores + softmax (2x2 per edge)
    if (tid < 16) {
        int el = tid >> 1, si = tid & 1;
        float s0 = 0.f, s1 = 0.f;
        for (int h = 0; h < 64; h++) {
            float qv = qs[el][si][h];
            s0 += qv * ks2[el][0][h];
            s1 += qv * ks2[el][1][h];
        }
        s0 *= 0.125f; s1 *= 0.125f;
        float m = fmaxf(s0, s1);
        float ea = __expf(s0 - m), eb = __expf(s1 - m);
        float inv = 1.f / (ea + eb);
        att[el][si][0] = ea * inv;
        att[el][si][1] = eb * inv;
    }
    __syncthreads();

    // attention output
#pragma unroll
    for (int el = 0; el < 8; el++)
        ys[el][s][c] = att[el][s][0] * vs[el][0][c] + att[el][s][1] * vs[el][1][c];
    __syncthreads();

    // @Wo + residual
    {
        float acc[8];
#pragma unroll
        for (int el = 0; el < 8; el++) acc[el] = 0.f;
        for (int k = 0; k < 64; k++) {
            float w = Wo[k * 64 + c];
#pragma unroll
            for (int el = 0; el < 8; el++) acc[el] += ys[el][s][k] * w;
        }
#pragma unroll
        for (int el = 0; el < 8; el++) xs[el][s][c] += acc[el];
    }
    __syncthreads();

    // LN1
    if (tid < 16) {
        int el = tid >> 1, si = tid & 1;
        float m = 0.f;
        for (int h = 0; h < 64; h++) m += xs[el][si][h];
        m *= (1.f / 64.f);
        float v = 0.f;
        for (int h = 0; h < 64; h++) { float d = xs[el][si][h] - m; v += d * d; }
        v *= (1.f / 64.f);
        mu[el][si] = m;
        rs[el][si] = rsqrtf(v + 1e-5f);
    }
    __syncthreads();
#pragma unroll
    for (int el = 0; el < 8; el++)
        xs[el][s][c] = (xs[el][s][c] - mu[el][s]) * rs[el][s];
    __syncthreads();

    // FFN: hid = relu(x @ W1)
    for (int j = 0; j < 4; j++) {
        float a[8];
#pragma unroll
        for (int el = 0; el < 8; el++) a[el] = 0.f;
        int f = j * 64 + c;
        for (int k = 0; k < 64; k++) {
            float w = W1[k * FFN_D + f];
#pragma unroll
            for (int el = 0; el < 8; el++) a[el] += xs[el][s][k] * w;
        }
#pragma unroll
        for (int el = 0; el < 8; el++) hid[el][s][f] = fmaxf(a[el], 0.f);
    }
    __syncthreads();

    // @W2 + residual
    {
        float acc[8];
#pragma unroll
        for (int el = 0; el < 8; el++) acc[el] = 0.f;
        for (int f = 0; f < FFN_D; f++) {
            float w = W2[f * 64 + c];
#pragma unroll
            for (int el = 0; el < 8; el++) acc[el] += hid[el][s][f] * w;
        }
#pragma unroll
        for (int el = 0; el < 8; el++) ys[el][s][c] = xs[el][s][c] + acc[el];
    }
    __syncthreads();

    // LN2 + store
    if (tid < 16) {
        int el = tid >> 1, si = tid & 1;
        float m = 0.f;
        for (int h = 0; h < 64; h++) m += ys[el][si][h];
        m *= (1.f / 64.f);
        float v = 0.f;
        for (int h = 0; h < 64; h++) { float d = ys[el][si][h] - m; v += d * d; }
        v *= (1.f / 64.f);
        mu[el][si] = m;
        rs[el][si] = rsqrtf(v + 1e-5f);
    }
    __syncthreads();
#pragma unroll
    for (int el = 0; el < 8; el++)
        g_x[((e0 + el) * 2 + s) * HID + c] = (ys[el][s][c] - mu[el][s]) * rs[el][s];
}

// ---------------- K4: lm head — exp(logits) written to out, partial row sums accumulated ----------------
// logits are bounded (|logit| ~ 0.2), so exp without max-subtraction is numerically safe.
__global__ __launch_bounds__(256) void k4_lmhead(const float* __restrict__ lmW,
                                                 const float* __restrict__ lmb,
                                                 float* __restrict__ out) {
    __shared__ float xsh[32][64];
    __shared__ float ssum[32];
    int rg = blockIdx.y;      // 0..127 row groups of 32
    int tid = threadIdx.x;    // 0..255
    for (int i = tid; i < 32 * 64; i += 256)
        xsh[i >> 6][i & 63] = g_x[rg * 32 * 64 + i];
    if (tid < 32) ssum[tid] = 0.f;
    __syncthreads();

    int c = blockIdx.x * 256 + tid;   // 0..31999
    float acc[32];
#pragma unroll
    for (int r = 0; r < 32; r++) acc[r] = 0.f;
    for (int k = 0; k < 64; k++) {
        float w = lmW[k * VOCAB + c];
#pragma unroll
        for (int r = 0; r < 32; r++) acc[r] += xsh[r][k] * w;
    }
    float bb = lmb[c];
    int lane = tid & 31;
#pragma unroll
    for (int r = 0; r < 32; r++) {
        float e = __expf(acc[r] + bb);
        out[(size_t)LBL_OFF + (size_t)(rg * 32 + r) * VOCAB + c] = e;
        float red = e;
        red += __shfl_xor_sync(0xFFFFFFFFu, red, 16);
        red += __shfl_xor_sync(0xFFFFFFFFu, red, 8);
        red += __shfl_xor_sync(0xFFFFFFFFu, red, 4);
        red += __shfl_xor_sync(0xFFFFFFFFu, red, 2);
        red += __shfl_xor_sync(0xFFFFFFFFu, red, 1);
        if (lane == 0) atomicAdd(&ssum[r], red);
    }
    __syncthreads();
    if (tid < 32) atomicAdd(&g_rowsum[rg * 32 + tid], ssum[tid]);
}

// ---------------- K5: in-place normalization ----------------
__global__ void k5_norm(float* __restrict__ out) {
    int row = blockIdx.x;
    float inv = 1.f / g_rowsum[row];
    size_t base = (size_t)LBL_OFF + (size_t)row * VOCAB;
    for (int c = threadIdx.x; c < VOCAB; c += blockDim.x)
        out[base + c] *= inv;
}

// ---------------- K6: labels ----------------
__global__ void k6_labels(const int* __restrict__ edge_tokens, float* __restrict__ out) {
    int idx = blockIdx.x * 256 + threadIdx.x;
    if (idx < N_EDGES * L_TOK) {
        int e = idx >> 3;
        int tok = edge_tokens[idx];
        int lab = (e == 0 && tok >= 4) ? tok : -100;
        out[idx] = (float)lab;
    }
}

// ---------------- launch ----------------
extern "C" void kernel_launch(void* const* d_in, const int* in_sizes, int n_in,
                              void* d_out, int out_size) {
    const int*   node_tokens = (const int*)d_in[0];
    const int*   edge_tokens = (const int*)d_in[1];
    const int*   edge_index  = (const int*)d_in[2];
    const float* emb    = (const float*)d_in[3];
    const float* W_self = (const float*)d_in[4];
    const float* W_nbr  = (const float*)d_in[5];
    const float* Wq     = (const float*)d_in[6];
    const float* Wk     = (const float*)d_in[7];
    const float* Wv     = (const float*)d_in[8];
    const float* Wo     = (const float*)d_in[9];
    const float* W1     = (const float*)d_in[10];
    const float* W2     = (const float*)d_in[11];
    const float* lmW    = (const float*)d_in[12];
    const float* lmb    = (const float*)d_in[13];
    float* out = (float*)d_out;

    k0_zero<<<2080, 128>>>(edge_index);
    k1_msg<<<128, 128>>>(node_tokens, edge_tokens, edge_index, emb, W_nbr);
    k2_h<<<256, 128>>>(node_tokens, edge_index, emb, W_self);
    k3_xform<<<256, 128>>>(Wq, Wk, Wv, Wo, W1, W2);
    k4_lmhead<<<dim3(125, 128), 256>>>(lmW, lmb, out);
    k5_norm<<<4096, 256>>>(out);
    k6_labels<<<64, 256>>>(edge_tokens, out);
}

// round 2
// speedup vs baseline: 2.0258x; 2.0258x over previous
#include <cuda_runtime.h>
#include <cstdint>

#define N_NODES 100000
#define N_EDGES 2048
#define L_TOK 8
#define HID 64
#define D_IN 512      // L_TOK * HID
#define D_GNN 128
#define VOCAB 32000
#define FFN_D 256
#define NROWS (N_EDGES * 2)   // 4096 lm-head rows
#define LBL_OFF 16384         // labels occupy [0, 16384)

// ---------------- device scratch (no allocations allowed) ----------------
__device__ float g_agg[N_NODES * D_GNN];    // only dst rows ever touched
__device__ float g_edge_h[N_EDGES * D_GNN];
__device__ float g_x[NROWS * HID];
__device__ float g_rowsum[NROWS];

// ---------------- K0: zero touched agg rows + row sums ----------------
__global__ void k0_zero(const int* __restrict__ edge_index) {
    int b = blockIdx.x, t = threadIdx.x;
    if (b < N_EDGES) {
        int dst = edge_index[N_EDGES + b];
        g_agg[dst * D_GNN + t] = 0.f;
    } else {
        int i = (b - N_EDGES) * 128 + t;
        if (i < NROWS) g_rowsum[i] = 0.f;
    }
}

// ---------------- K1: msg = (node_emb[src] + edge_emb) @ W_nbr; scatter-add at dst ----------------
__global__ void k1_msg(const int* __restrict__ node_tokens,
                       const int* __restrict__ edge_tokens,
                       const int* __restrict__ edge_index,
                       const float* __restrict__ emb,
                       const float* __restrict__ W_nbr) {
    __shared__ float t_s[16][D_IN];
    __shared__ int s_src[16], s_dst[16];
    int b = blockIdx.x, tid = threadIdx.x;
    int e0 = b * 16;
    if (tid < 16) {
        s_src[tid] = edge_index[e0 + tid];
        s_dst[tid] = edge_index[N_EDGES + e0 + tid];
    }
    __syncthreads();
    for (int el = 0; el < 16; el++) {
        int e = e0 + el;
        int sn = s_src[el];
        for (int idx = tid; idx < D_IN; idx += 128) {
            int l = idx >> 6, h = idx & 63;
            int tn = node_tokens[sn * L_TOK + l];
            int te = edge_tokens[e * L_TOK + l];
            t_s[el][idx] = emb[tn * HID + h] + emb[te * HID + h];
        }
    }
    __syncthreads();
    float acc[16];
#pragma unroll
    for (int el = 0; el < 16; el++) acc[el] = 0.f;
    for (int k = 0; k < D_IN; k++) {
        float w = W_nbr[k * D_GNN + tid];
#pragma unroll
        for (int el = 0; el < 16; el++) acc[el] += t_s[el][k] * w;
    }
#pragma unroll
    for (int el = 0; el < 16; el++)
        atomicAdd(&g_agg[s_dst[el] * D_GNN + tid], acc[el]);
}

// ---------------- K2: h = relu(node_emb @ W_self + agg) at endpoints; edge_h = h_src+h_dst ----------------
__global__ void k2_h(const int* __restrict__ node_tokens,
                     const int* __restrict__ edge_index,
                     const float* __restrict__ emb,
                     const float* __restrict__ W_self) {
    __shared__ float ne[16][D_IN];
    __shared__ int s_node[16];
    int b = blockIdx.x, tid = threadIdx.x;
    int e0 = b * 8;
    if (tid < 16) {
        int el = tid & 7;
        s_node[tid] = (tid < 8) ? edge_index[e0 + el] : edge_index[N_EDGES + e0 + el];
    }
    __syncthreads();
    for (int r = 0; r < 16; r++) {
        int n = s_node[r];
        for (int idx = tid; idx < D_IN; idx += 128) {
            int l = idx >> 6, h = idx & 63;
            int tn = node_tokens[n * L_TOK + l];
            ne[r][idx] = emb[tn * HID + h];
        }
    }
    __syncthreads();
    float acc[16];
#pragma unroll
    for (int r = 0; r < 16; r++) acc[r] = 0.f;
    for (int k = 0; k < D_IN; k++) {
        float w = W_self[k * D_GNN + tid];
#pragma unroll
        for (int r = 0; r < 16; r++) acc[r] += ne[r][k] * w;
    }
#pragma unroll
    for (int el = 0; el < 8; el++) {
        float hs = fmaxf(acc[el]     + g_agg[s_node[el]     * D_GNN + tid], 0.f);
        float hd = fmaxf(acc[el + 8] + g_agg[s_node[el + 8] * D_GNN + tid], 0.f);
        g_edge_h[(e0 + el) * D_GNN + tid] = hs + hd;
    }
}

// ---------------- K3: transformer block — one warp per (edge, seq) row ----------------
__global__ __launch_bounds__(512) void k3_xform(const float* __restrict__ Wq, const float* __restrict__ Wk,
                                                const float* __restrict__ Wv, const float* __restrict__ Wo,
                                                const float* __restrict__ W1, const float* __restrict__ W2) {
    __shared__ float2 ksm[8][2][32];
    __shared__ float2 vsm[8][2][32];
    int tid = threadIdx.x, lane = tid & 31, wid = tid >> 5;
    int el = wid >> 1, s = wid & 1;
    int e = blockIdx.x * 8 + el;

    const float2* xg = (const float2*)g_edge_h;
    float2 xv = xg[e * 64 + s * 32 + lane];
    float x0 = xv.x, x1 = xv.y;   // elements 2*lane, 2*lane+1

    const float2* Wq2 = (const float2*)Wq;
    const float2* Wk2 = (const float2*)Wk;
    const float2* Wv2 = (const float2*)Wv;
    const float2* Wo2 = (const float2*)Wo;
    const float2* W22 = (const float2*)W2;

    // q,k,v for this row: per lane two output cols
    float q0 = 0.f, q1 = 0.f, kk0 = 0.f, kk1 = 0.f, v0 = 0.f, v1 = 0.f;
#pragma unroll 8
    for (int k = 0; k < 64; k++) {
        float src = (k & 1) ? x1 : x0;
        float xk = __shfl_sync(0xffffffffu, src, k >> 1);
        float2 wq = Wq2[k * 32 + lane];
        float2 wk = Wk2[k * 32 + lane];
        float2 wv = Wv2[k * 32 + lane];
        q0 += xk * wq.x; q1 += xk * wq.y;
        kk0 += xk * wk.x; kk1 += xk * wk.y;
        v0 += xk * wv.x; v1 += xk * wv.y;
    }
    ksm[el][s][lane] = make_float2(kk0, kk1);
    vsm[el][s][lane] = make_float2(v0, v1);
    __syncthreads();

    // scores + softmax (each row attends over the 2 seq positions of its edge)
    float2 k0r = ksm[el][0][lane], k1r = ksm[el][1][lane];
    float p0 = q0 * k0r.x + q1 * k0r.y;
    float p1 = q0 * k1r.x + q1 * k1r.y;
#pragma unroll
    for (int d = 16; d; d >>= 1) {
        p0 += __shfl_xor_sync(0xffffffffu, p0, d);
        p1 += __shfl_xor_sync(0xffffffffu, p1, d);
    }
    p0 *= 0.125f; p1 *= 0.125f;
    float m = fmaxf(p0, p1);
    float ea = __expf(p0 - m), eb = __expf(p1 - m);
    float inv = 1.f / (ea + eb);
    float a0 = ea * inv, a1 = eb * inv;

    float2 v0r = vsm[el][0][lane], v1r = vsm[el][1][lane];
    float y0 = a0 * v0r.x + a1 * v1r.x;
    float y1 = a0 * v0r.y + a1 * v1r.y;

    // @Wo + residual
    float o0 = 0.f, o1 = 0.f;
#pragma unroll 8
    for (int k = 0; k < 64; k++) {
        float src = (k & 1) ? y1 : y0;
        float yk = __shfl_sync(0xffffffffu, src, k >> 1);
        float2 wo = Wo2[k * 32 + lane];
        o0 += yk * wo.x; o1 += yk * wo.y;
    }
    x0 += o0; x1 += o1;

    // LN1 (warp reduce)
    float msum = x0 + x1;
#pragma unroll
    for (int d = 16; d; d >>= 1) msum += __shfl_xor_sync(0xffffffffu, msum, d);
    float mean = msum * (1.f / 64.f);
    float d0 = x0 - mean, d1 = x1 - mean;
    float vsum = d0 * d0 + d1 * d1;
#pragma unroll
    for (int d = 16; d; d >>= 1) vsum += __shfl_xor_sync(0xffffffffu, vsum, d);
    float rstd = rsqrtf(vsum * (1.f / 64.f) + 1e-5f);
    x0 = d0 * rstd; x1 = d1 * rstd;

    // FFN: hid = relu(x @ W1), lane owns f = j*32 + lane
    float h[8];
#pragma unroll
    for (int j = 0; j < 8; j++) h[j] = 0.f;
#pragma unroll 4
    for (int k = 0; k < 64; k++) {
        float src = (k & 1) ? x1 : x0;
        float xk = __shfl_sync(0xffffffffu, src, k >> 1);
        const float* w1r = W1 + k * FFN_D + lane;
#pragma unroll
        for (int j = 0; j < 8; j++) h[j] += xk * w1r[j * 32];
    }
#pragma unroll
    for (int j = 0; j < 8; j++) h[j] = fmaxf(h[j], 0.f);

    // @W2 + residual
    float o20 = 0.f, o21 = 0.f;
#pragma unroll
    for (int j = 0; j < 8; j++) {
        float hj = h[j];
#pragma unroll 8
        for (int l = 0; l < 32; l++) {
            float hf = __shfl_sync(0xffffffffu, hj, l);
            int f = j * 32 + l;
            float2 w2 = W22[f * 32 + lane];
            o20 += hf * w2.x; o21 += hf * w2.y;
        }
    }
    float z0 = x0 + o20, z1 = x1 + o21;

    // LN2 + store
    msum = z0 + z1;
#pragma unroll
    for (int d = 16; d; d >>= 1) msum += __shfl_xor_sync(0xffffffffu, msum, d);
    mean = msum * (1.f / 64.f);
    d0 = z0 - mean; d1 = z1 - mean;
    vsum = d0 * d0 + d1 * d1;
#pragma unroll
    for (int d = 16; d; d >>= 1) vsum += __shfl_xor_sync(0xffffffffu, vsum, d);
    rstd = rsqrtf(vsum * (1.f / 64.f) + 1e-5f);
    float2* gx2 = (float2*)g_x;
    gx2[(e * 2 + s) * 32 + lane] = make_float2(d0 * rstd, d1 * rstd);
}

// ---------------- K4: lm head via tf32 mma.sync (two-pass softmax) ----------------
// Pass A (STORE=false): GEMM + exp + rowsum atomics, no probs store.
// Pass B (STORE=true):  GEMM + exp * (1/rowsum), store probs.
#define XS_STRIDE 68
#define SMEM_K4 (2 * 128 * 68 * 4 + 512)

template <bool STORE>
__global__ __launch_bounds__(256) void k4_tc(const float* __restrict__ lmW,
                                             const float* __restrict__ lmb,
                                             float* __restrict__ out) {
    extern __shared__ uint32_t dsm[];
    uint32_t* xs = dsm;                 // [128][68] tf32 x tile (rows x k)
    uint32_t* wT = dsm + 128 * 68;      // [128][68] tf32 W tile, n-major (n x k)
    float* bsm = (float*)(dsm + 2 * 128 * 68);

    int tid = threadIdx.x;
    int cb = blockIdx.x * 128;
    int rb = blockIdx.y * 128;

    for (int i = tid; i < 128 * 64; i += 256) {
        int r = i >> 6, c = i & 63;
        float v = g_x[(rb + r) * 64 + c];
        uint32_t u; asm("cvt.rna.tf32.f32 %0, %1;" : "=r"(u) : "f"(v));
        xs[r * XS_STRIDE + c] = u;
    }
    for (int i = tid; i < 64 * 128; i += 256) {
        int k = i >> 7, n = i & 127;
        float v = lmW[(size_t)k * VOCAB + cb + n];
        uint32_t u; asm("cvt.rna.tf32.f32 %0, %1;" : "=r"(u) : "f"(v));
        wT[n * XS_STRIDE + k] = u;
    }
    if (tid < 128) bsm[tid] = lmb[cb + tid];
    __syncthreads();

    int lane = tid & 31, warp = tid >> 5;
    int g = lane >> 2, tig = lane & 3;
    int wr = warp * 16;   // warp tile: 16 rows x 128 cols

    float acc[16][4];
#pragma unroll
    for (int nt = 0; nt < 16; nt++) {
        acc[nt][0] = 0.f; acc[nt][1] = 0.f; acc[nt][2] = 0.f; acc[nt][3] = 0.f;
    }

#pragma unroll
    for (int ks = 0; ks < 8; ks++) {
        int k0 = ks * 8;
        uint32_t a0 = xs[(wr + g) * XS_STRIDE + k0 + tig];
        uint32_t a1 = xs[(wr + 8 + g) * XS_STRIDE + k0 + tig];
        uint32_t a2 = xs[(wr + g) * XS_STRIDE + k0 + 4 + tig];
        uint32_t a3 = xs[(wr + 8 + g) * XS_STRIDE + k0 + 4 + tig];
#pragma unroll
        for (int nt = 0; nt < 16; nt++) {
            uint32_t b0 = wT[(nt * 8 + g) * XS_STRIDE + k0 + tig];
            uint32_t b1 = wT[(nt * 8 + g) * XS_STRIDE + k0 + 4 + tig];
            asm volatile(
                "mma.sync.aligned.m16n8k8.row.col.f32.tf32.tf32.f32 "
                "{%0,%1,%2,%3}, {%4,%5,%6,%7}, {%8,%9}, {%0,%1,%2,%3};\n"
                : "+f"(acc[nt][0]), "+f"(acc[nt][1]), "+f"(acc[nt][2]), "+f"(acc[nt][3])
                : "r"(a0), "r"(a1), "r"(a2), "r"(a3), "r"(b0), "r"(b1));
        }
    }

    int r_lo = rb + wr + g, r_hi = r_lo + 8;
    if (STORE) {
        float inv_lo = 1.f / g_rowsum[r_lo];
        float inv_hi = 1.f / g_rowsum[r_hi];
#pragma unroll
        for (int nt = 0; nt < 16; nt++) {
            int c = nt * 8 + 2 * tig;
            float b0v = bsm[c], b1v = bsm[c + 1];
            float e0 = __expf(acc[nt][0] + b0v) * inv_lo;
            float e1 = __expf(acc[nt][1] + b1v) * inv_lo;
            float e2 = __expf(acc[nt][2] + b0v) * inv_hi;
            float e3 = __expf(acc[nt][3] + b1v) * inv_hi;
            size_t base = (size_t)LBL_OFF + (size_t)cb + c;
            *(float2*)&out[base + (size_t)r_lo * VOCAB] = make_float2(e0, e1);
            *(float2*)&out[base + (size_t)r_hi * VOCAB] = make_float2(e2, e3);
        }
    } else {
        float slo = 0.f, shi = 0.f;
#pragma unroll
        for (int nt = 0; nt < 16; nt++) {
            int c = nt * 8 + 2 * tig;
            float b0v = bsm[c], b1v = bsm[c + 1];
            slo += __expf(acc[nt][0] + b0v) + __expf(acc[nt][1] + b1v);
            shi += __expf(acc[nt][2] + b0v) + __expf(acc[nt][3] + b1v);
        }
        slo += __shfl_xor_sync(0xffffffffu, slo, 1);
        slo += __shfl_xor_sync(0xffffffffu, slo, 2);
        shi += __shfl_xor_sync(0xffffffffu, shi, 1);
        shi += __shfl_xor_sync(0xffffffffu, shi, 2);
        if (tig == 0) {
            atomicAdd(&g_rowsum[r_lo], slo);
            atomicAdd(&g_rowsum[r_hi], shi);
        }
    }
}

// ---------------- K6: labels ----------------
__global__ void k6_labels(const int* __restrict__ edge_tokens, float* __restrict__ out) {
    int idx = blockIdx.x * 256 + threadIdx.x;
    if (idx < N_EDGES * L_TOK) {
        int e = idx >> 3;
        int tok = edge_tokens[idx];
        int lab = (e == 0 && tok >= 4) ? tok : -100;
        out[idx] = (float)lab;
    }
}

// ---------------- launch ----------------
extern "C" void kernel_launch(void* const* d_in, const int* in_sizes, int n_in,
                              void* d_out, int out_size) {
    const int*   node_tokens = (const int*)d_in[0];
    const int*   edge_tokens = (const int*)d_in[1];
    const int*   edge_index  = (const int*)d_in[2];
    const float* emb    = (const float*)d_in[3];
    const float* W_self = (const float*)d_in[4];
    const float* W_nbr  = (const float*)d_in[5];
    const float* Wq     = (const float*)d_in[6];
    const float* Wk     = (const float*)d_in[7];
    const float* Wv     = (const float*)d_in[8];
    const float* Wo     = (const float*)d_in[9];
    const float* W1     = (const float*)d_in[10];
    const float* W2     = (const float*)d_in[11];
    const float* lmW    = (const float*)d_in[12];
    const float* lmb    = (const float*)d_in[13];
    float* out = (float*)d_out;

    cudaFuncSetAttribute(k4_tc<false>, cudaFuncAttributeMaxDynamicSharedMemorySize, SMEM_K4);
    cudaFuncSetAttribute(k4_tc<true>,  cudaFuncAttributeMaxDynamicSharedMemorySize, SMEM_K4);

    k0_zero<<<2080, 128>>>(edge_index);
    k1_msg<<<128, 128>>>(node_tokens, edge_tokens, edge_index, emb, W_nbr);
    k2_h<<<256, 128>>>(node_tokens, edge_index, emb, W_self);
    k3_xform<<<256, 512>>>(Wq, Wk, Wv, Wo, W1, W2);
    k4_tc<false><<<dim3(250, 32), 256, SMEM_K4>>>(lmW, lmb, out);
    k4_tc<true><<<dim3(250, 32), 256, SMEM_K4>>>(lmW, lmb, out);
    k6_labels<<<64, 256>>>(edge_tokens, out);
}